// round 2
// baseline (speedup 1.0000x reference)
#include <cuda_runtime.h>
#include <cuda_bf16.h>

// out[m,n] = tanh( sum_h w2[h] * tanh( w1[h][0]*A[m,n] + w1[h][1]*pre[n]
//                                    + w1[h][2]*post[m] + b1[h] ) + b2 )
// M = N = 4096, Nh = 8.
//
// MUFU-bound kernel: 9 x tanh.approx.f32 per element.

#define NH 8

__device__ __forceinline__ float htanh(float x) {
    float y;
    asm("tanh.approx.f32 %0, %1;" : "=f"(y) : "f"(x));
    return y;
}

__global__ __launch_bounds__(256) void synapse_kernel(
    const float* __restrict__ A,
    const float* __restrict__ pre,
    const float* __restrict__ post,
    const float* __restrict__ w1,   // [NH, 3]
    const float* __restrict__ b1,   // [NH]
    const float* __restrict__ w2,   // [1, NH]
    const float* __restrict__ b2,   // [1]
    float* __restrict__ out,
    int M, int N)
{
    // Each thread handles 8 consecutive floats (2 float4) of one row.
    const int n4 = N >> 2;                     // float4s per row
    long long tid = (long long)blockIdx.x * blockDim.x + threadIdx.x;
    long long f = tid * 2;                     // first float4 index (global)
    int row  = (int)(f / n4);
    int col4 = (int)(f - (long long)row * n4); // float4 index within row
    if (row >= M) return;

    // Load tiny weight tensors (L1/L2 cached, amortized over 8 elements).
    float w10[NH], w11[NH], t[NH], v2[NH];
    const float pm = __ldg(&post[row]);
#pragma unroll
    for (int h = 0; h < NH; ++h) {
        w10[h] = __ldg(&w1[h * 3 + 0]);
        w11[h] = __ldg(&w1[h * 3 + 1]);
        float w12 = __ldg(&w1[h * 3 + 2]);
        t[h] = fmaf(w12, pm, __ldg(&b1[h]));   // per-row hoisted term
        v2[h] = __ldg(&w2[h]);
    }
    const float bb2 = __ldg(&b2[0]);

    const float4* A4   = (const float4*)A;
    const float4* P4   = (const float4*)pre;
    float4*       O4   = (float4*)out;

#pragma unroll
    for (int j = 0; j < 2; ++j) {
        long long idx = f + j;
        float4 a = __ldg(&A4[idx]);
        float4 p = __ldg(&P4[col4 + j]);

        float av[4] = {a.x, a.y, a.z, a.w};
        float pv[4] = {p.x, p.y, p.z, p.w};
        float ov[4];

#pragma unroll
        for (int k = 0; k < 4; ++k) {
            float acc = bb2;
#pragma unroll
            for (int h = 0; h < NH; ++h) {
                float arg = fmaf(w10[h], av[k], fmaf(w11[h], pv[k], t[h]));
                acc = fmaf(v2[h], htanh(arg), acc);
            }
            ov[k] = htanh(acc);
        }

        float4 o;
        o.x = ov[0]; o.y = ov[1]; o.z = ov[2]; o.w = ov[3];
        O4[idx] = o;
    }
}

extern "C" void kernel_launch(void* const* d_in, const int* in_sizes, int n_in,
                              void* d_out, int out_size) {
    const float* A    = (const float*)d_in[0];
    const float* pre  = (const float*)d_in[1];
    const float* post = (const float*)d_in[2];
    const float* w1   = (const float*)d_in[3];
    const float* b1   = (const float*)d_in[4];
    const float* w2   = (const float*)d_in[5];
    const float* b2   = (const float*)d_in[6];
    float* out = (float*)d_out;

    int N = in_sizes[1];          // len(pre) = 4096
    int M = in_sizes[2];          // len(post) = 4096

    long long total = (long long)M * N;
    long long threads_needed = total / 8;          // 8 elems per thread
    int block = 256;
    int grid = (int)((threads_needed + block - 1) / block);

    synapse_kernel<<<grid, block>>>(A, pre, post, w1, b1, w2, b2, out, M, N);
}

// round 11
// speedup vs baseline: 1.0225x; 1.0225x over previous
#include <cuda_runtime.h>
#include <cuda_fp16.h>
#include <cuda_bf16.h>

// out[m,n] = tanh( sum_h w2[h] * tanh( w1[h][0]*A[m,n] + w1[h][1]*pre[n]
//                                    + w1[h][2]*post[m] + b1[h] ) + b2 )
// M = N = 4096, Nh = 8.
//
// MUFU-bound. Inner 8 tanh evaluated pairwise (2 elements at once) via
// tanh.approx.f16x2 -> 5 MUFU ops/element instead of 9. Args computed and
// accumulated in f32 for precision.

#define NH 8

__device__ __forceinline__ float htanh(float x) {
    float y;
    asm("tanh.approx.f32 %0, %1;" : "=f"(y) : "f"(x));
    return y;
}

__device__ __forceinline__ __half2 htanh2(__half2 x) {
    __half2 y;
    asm("tanh.approx.f16x2 %0, %1;"
        : "=r"(*(unsigned int*)&y) : "r"(*(const unsigned int*)&x));
    return y;
}

__global__ __launch_bounds__(256) void synapse_kernel(
    const float* __restrict__ A,
    const float* __restrict__ pre,
    const float* __restrict__ post,
    const float* __restrict__ w1,   // [NH, 3]
    const float* __restrict__ b1,   // [NH]
    const float* __restrict__ w2,   // [1, NH]
    const float* __restrict__ b2,   // [1]
    float* __restrict__ out,
    int M, int N)
{
    // Each thread handles 8 consecutive floats (2 float4) of one row.
    const int n4 = N >> 2;                     // float4s per row
    long long tid = (long long)blockIdx.x * blockDim.x + threadIdx.x;
    long long f = tid * 2;                     // first float4 index (global)
    int row  = (int)(f / n4);
    int col4 = (int)(f - (long long)row * n4); // float4 index within row
    if (row >= M) return;

    // Tiny weight tensors (L1/L2 cached, amortized over 8 elements).
    float w10[NH], w11[NH], t[NH], v2[NH];
    const float pm = __ldg(&post[row]);
#pragma unroll
    for (int h = 0; h < NH; ++h) {
        w10[h] = __ldg(&w1[h * 3 + 0]);
        w11[h] = __ldg(&w1[h * 3 + 1]);
        float w12 = __ldg(&w1[h * 3 + 2]);
        t[h] = fmaf(w12, pm, __ldg(&b1[h]));   // per-row hoisted term
        v2[h] = __ldg(&w2[h]);
    }
    const float bb2 = __ldg(&b2[0]);

    const float4* A4 = (const float4*)A;
    const float4* P4 = (const float4*)pre;
    float4*       O4 = (float4*)out;

#pragma unroll
    for (int j = 0; j < 2; ++j) {
        long long idx = f + j;
        float4 a = __ldg(&A4[idx]);
        float4 p = __ldg(&P4[col4 + j]);

        float av[4] = {a.x, a.y, a.z, a.w};
        float pv[4] = {p.x, p.y, p.z, p.w};
        float ov[4];

        // Process the 4 elements as 2 pairs; each pair shares one f16x2 tanh
        // per hidden unit.
#pragma unroll
        for (int q = 0; q < 2; ++q) {
            const int e0 = 2 * q, e1 = 2 * q + 1;
            float acc0 = bb2, acc1 = bb2;
#pragma unroll
            for (int h = 0; h < NH; ++h) {
                float arg0 = fmaf(w10[h], av[e0], fmaf(w11[h], pv[e0], t[h]));
                float arg1 = fmaf(w10[h], av[e1], fmaf(w11[h], pv[e1], t[h]));
                __half2 ar = __floats2half2_rn(arg0, arg1);
                __half2 th = htanh2(ar);
                float2 tf = __half22float2(th);
                acc0 = fmaf(v2[h], tf.x, acc0);
                acc1 = fmaf(v2[h], tf.y, acc1);
            }
            ov[e0] = htanh(acc0);
            ov[e1] = htanh(acc1);
        }

        float4 o;
        o.x = ov[0]; o.y = ov[1]; o.z = ov[2]; o.w = ov[3];
        O4[idx] = o;
    }
}

extern "C" void kernel_launch(void* const* d_in, const int* in_sizes, int n_in,
                              void* d_out, int out_size) {
    const float* A    = (const float*)d_in[0];
    const float* pre  = (const float*)d_in[1];
    const float* post = (const float*)d_in[2];
    const float* w1   = (const float*)d_in[3];
    const float* b1   = (const float*)d_in[4];
    const float* w2   = (const float*)d_in[5];
    const float* b2   = (const float*)d_in[6];
    float* out = (float*)d_out;

    int N = in_sizes[1];          // len(pre) = 4096
    int M = in_sizes[2];          // len(post) = 4096

    long long total = (long long)M * N;
    long long threads_needed = total / 8;          // 8 elems per thread
    int block = 256;
    int grid = (int)((threads_needed + block - 1) / block);

    synapse_kernel<<<grid, block>>>(A, pre, post, w1, b1, w2, b2, out, M, N);
}